// round 7
// baseline (speedup 1.0000x reference)
#include <cuda_runtime.h>
#include <cuda_bf16.h>
#include <math.h>
#include <stdint.h>

#define NROWS 8192
#define NC    256
#define NWORDS (NC/2)          // 128 uint32 per row (bf16x2) — fp8 rows also 128 words

// ---------------- scratch ----------------------------------------------------
__device__ float    g_nrm[4][NROWS * NC];       // normalized fp32 (v,t,pv,pt)
__device__ unsigned g_bhi[4][NROWS * NWORDS];   // bf16 hi (A-role mats pre-scaled x512)
__device__ unsigned g_f8 [4][NROWS * NWORDS];   // fp8 rows: A-role [hi|512*lo], B-role [512*lo|hi]
__device__ float    g_d1[NROWS];                // v_i . pt_i
__device__ float    g_d2[NROWS];                // t_i . pv_i
__device__ float    g_cs[4][64][NC];
__device__ float    g_cq[4][64][NC];
__device__ int      g_cnt[2][NROWS];            // global rank counters

// ---------------- small helpers ----------------------------------------------
__device__ __forceinline__ uint32_t smem_u32(const void* p) {
    uint32_t a;
    asm("{ .reg .u64 t; cvta.to.shared.u64 t, %1; cvt.u32.u64 %0, t; }"
        : "=r"(a) : "l"(p));
    return a;
}

#define CP_ASYNC16(dst, src)                                                   \
    asm volatile("cp.async.cg.shared.global [%0], [%1], 16;"                   \
                 :: "r"(dst), "l"(src) : "memory")
#define CP_COMMIT()  asm volatile("cp.async.commit_group;" ::: "memory")
#define CP_WAIT1()   asm volatile("cp.async.wait_group 1;" ::: "memory")

#define LDSM_X4(r0, r1, r2, r3, addr)                                          \
    asm volatile("ldmatrix.sync.aligned.m8n8.x4.shared.b16 {%0,%1,%2,%3}, [%4];" \
                 : "=r"(r0), "=r"(r1), "=r"(r2), "=r"(r3) : "r"(addr))

#define MMA16816(d, a, b0, b1)                                                 \
    asm volatile("mma.sync.aligned.m16n8k16.row.col.f32.bf16.bf16.f32 "        \
                 "{%0,%1,%2,%3}, {%4,%5,%6,%7}, {%8,%9}, {%0,%1,%2,%3};"       \
                 : "+f"((d)[0]), "+f"((d)[1]), "+f"((d)[2]), "+f"((d)[3])      \
                 : "r"((a)[0]), "r"((a)[1]), "r"((a)[2]), "r"((a)[3]),         \
                   "r"(b0), "r"(b1))

#define MMAFP832(d, a, b0, b1)                                                 \
    asm volatile("mma.sync.aligned.m16n8k32.row.col.f32.e4m3.e4m3.f32 "        \
                 "{%0,%1,%2,%3}, {%4,%5,%6,%7}, {%8,%9}, {%0,%1,%2,%3};"       \
                 : "+f"((d)[0]), "+f"((d)[1]), "+f"((d)[2]), "+f"((d)[3])      \
                 : "r"((a)[0]), "r"((a)[1]), "r"((a)[2]), "r"((a)[3]),         \
                   "r"(b0), "r"(b1))

// ---------------- 1. normalize + bf16 hi / fp8 split -------------------------
__device__ __forceinline__ unsigned pack2f(float a, float b) {
    __nv_bfloat16 ha = __float2bfloat16_rn(a), hb = __float2bfloat16_rn(b);
    return (unsigned)__bfloat16_as_ushort(ha)
         | ((unsigned)__bfloat16_as_ushort(hb) << 16);
}
__device__ __forceinline__ unsigned pack_fp8x4(float a, float b, float c, float d) {
    unsigned short lo, hi;
    asm("cvt.rn.satfinite.e4m3x2.f32 %0, %1, %2;" : "=h"(lo) : "f"(b), "f"(a));
    asm("cvt.rn.satfinite.e4m3x2.f32 %0, %1, %2;" : "=h"(hi) : "f"(d), "f"(c));
    return (unsigned)lo | ((unsigned)hi << 16);
}

__global__ void normalize_kernel(const float* __restrict__ v,
                                 const float* __restrict__ t,
                                 const float* __restrict__ pv,
                                 const float* __restrict__ pt) {
    int y = blockIdx.y;
    const float* src = (y == 0) ? v : (y == 1) ? t : (y == 2) ? pv : pt;
    int warp = threadIdx.x >> 5, lane = threadIdx.x & 31;
    int row = blockIdx.x * 8 + warp;
    const float4* s4 = (const float4*)(src + (size_t)row * NC);
    float4 x0 = s4[lane];
    float4 x1 = s4[lane + 32];
    float ss = x0.x*x0.x + x0.y*x0.y + x0.z*x0.z + x0.w*x0.w
             + x1.x*x1.x + x1.y*x1.y + x1.z*x1.z + x1.w*x1.w;
    #pragma unroll
    for (int o = 16; o; o >>= 1) ss += __shfl_xor_sync(0xffffffffu, ss, o);
    float r = 1.0f / fmaxf(sqrtf(ss), 1e-12f);
    x0.x *= r; x0.y *= r; x0.z *= r; x0.w *= r;
    x1.x *= r; x1.y *= r; x1.z *= r; x1.w *= r;
    float4* d4 = (float4*)(g_nrm[y] + (size_t)row * NC);
    d4[lane] = x0;
    d4[lane + 32] = x1;

    float xs[8] = { x0.x, x0.y, x0.z, x0.w, x1.x, x1.y, x1.z, x1.w };
    float h[8], l[8];
    #pragma unroll
    for (int i = 0; i < 8; i++) {
        __nv_bfloat16 hb = __float2bfloat16_rn(xs[i]);
        h[i] = __bfloat162float(hb);
        l[i] = (xs[i] - h[i]) * 512.0f;       // scaled lo
    }
    const float sc = (y < 2) ? 512.0f : 1.0f; // A-role hi pre-scaled (exact)
    size_t rb = (size_t)row * NWORDS;
    g_bhi[y][rb + 2*lane]      = pack2f(h[0]*sc, h[1]*sc);
    g_bhi[y][rb + 2*lane + 1]  = pack2f(h[2]*sc, h[3]*sc);
    g_bhi[y][rb + 64 + 2*lane] = pack2f(h[4]*sc, h[5]*sc);
    g_bhi[y][rb + 65 + 2*lane] = pack2f(h[6]*sc, h[7]*sc);

    // fp8 rows: A-role (y<2): [fp8(hi) | fp8(512 lo)]; B-role: [fp8(512 lo) | fp8(hi)]
    unsigned hw0 = pack_fp8x4(h[0], h[1], h[2], h[3]);
    unsigned hw1 = pack_fp8x4(h[4], h[5], h[6], h[7]);
    unsigned lw0 = pack_fp8x4(l[0], l[1], l[2], l[3]);
    unsigned lw1 = pack_fp8x4(l[4], l[5], l[6], l[7]);
    int hbase = (y < 2) ? 0 : 64;
    int lbase = 64 - hbase;
    g_f8[y][rb + hbase + lane]      = hw0;
    g_f8[y][rb + hbase + 32 + lane] = hw1;
    g_f8[y][rb + lbase + lane]      = lw0;
    g_f8[y][rb + lbase + 32 + lane] = lw1;
}

// ---------------- 2. per-column partial sums --------------------------------
__global__ void colstats_kernel() {
    const float* X = g_nrm[blockIdx.y];
    int col = threadIdx.x;
    int r0 = blockIdx.x * 128;
    float s = 0.f, q = 0.f;
    #pragma unroll 4
    for (int r = 0; r < 128; r++) {
        float x = X[(size_t)(r0 + r) * NC + col];
        s += x; q += x * x;
    }
    g_cs[blockIdx.y][blockIdx.x][col] = s;
    g_cq[blockIdx.y][blockIdx.x][col] = q;
}

// ---------------- 3. diagonals + zero count buffer --------------------------
__global__ void diag_kernel() {
    int warp = threadIdx.x >> 5, lane = threadIdx.x & 31;
    int row = blockIdx.x * 8 + warp;
    int zi = blockIdx.x * 256 + threadIdx.x;
    if (zi < 2 * NROWS) ((int*)g_cnt)[zi] = 0;

    size_t base = (size_t)row * NC;
    const float4* a = (const float4*)(g_nrm[0] + base);
    const float4* b = (const float4*)(g_nrm[3] + base);
    const float4* c = (const float4*)(g_nrm[1] + base);
    const float4* d = (const float4*)(g_nrm[2] + base);
    float4 a0 = a[lane], a1 = a[lane+32], b0 = b[lane], b1 = b[lane+32];
    float4 c0 = c[lane], c1 = c[lane+32], d0 = d[lane], d1 = d[lane+32];
    float s1 = a0.x*b0.x + a0.y*b0.y + a0.z*b0.z + a0.w*b0.w
             + a1.x*b1.x + a1.y*b1.y + a1.z*b1.z + a1.w*b1.w;
    float s2 = c0.x*d0.x + c0.y*d0.y + c0.z*d0.z + c0.w*d0.w
             + c1.x*d1.x + c1.y*d1.y + c1.z*d1.z + c1.w*d1.w;
    #pragma unroll
    for (int o = 16; o; o >>= 1) {
        s1 += __shfl_xor_sync(0xffffffffu, s1, o);
        s2 += __shfl_xor_sync(0xffffffffu, s2, o);
    }
    if (lane == 0) { g_d1[row] = s1; g_d2[row] = s2; }
}

// ---------------- 4. HMMA/QMMA GEMM + rank count ----------------------------
// acc = 512*s: chunks 0-3 bf16 (512Ahi . Bhi, k64 each), chunks 4-7 fp8
// ([Ahi|512Alo].[512Blo|Bhi], k128 each). BM=BN=128, 4 warps 2x2, warp 64x64.
#define A_BYTES  16384
#define B_BYTES  16384
#define STAGE_B  (A_BYTES + B_BYTES)
#define STAGES   3
#define DYN_SMEM (STAGES * STAGE_B + 1024)
#define NCHUNK   8
#define JSPLIT   4
#define NJT      (64 / JSPLIT)
#define TOTAL    (NJT * NCHUNK)

__global__ void __launch_bounds__(128, 2) count_kernel() {
    extern __shared__ char dynsm[];
    __shared__ int scnt[128];

    const int t = threadIdx.x;
    const int lane = t & 31;
    const int wid = t >> 5;
    const int warp_m = wid & 1;
    const int warp_n = wid >> 1;
    const int mat = blockIdx.y;
    const int i0 = blockIdx.x * 128;
    const int jt0 = blockIdx.z * NJT;

    const unsigned* __restrict__ Abf = g_bhi[mat ? 1 : 0];
    const unsigned* __restrict__ Af8 = g_f8 [mat ? 1 : 0];
    const unsigned* __restrict__ Bbf = g_bhi[mat ? 2 : 3];
    const unsigned* __restrict__ Bf8 = g_f8 [mat ? 2 : 3];
    const float*    __restrict__ diag = mat ? g_d2 : g_d1;

    const unsigned sb = (smem_u32(dynsm) + 1023u) & ~1023u;

    if (t < 128) scnt[t] = 0;

    const int lg_r = t >> 3;             // 0..15
    const int lg_q = t & 7;
    const unsigned swq = ((unsigned)(lg_q ^ (lg_r & 7))) << 4;

    float dva[4], dvb[4];
    #pragma unroll
    for (int mt = 0; mt < 4; mt++) {
        int ra = i0 + warp_m * 64 + mt * 16 + (lane >> 2);
        dva[mt] = 512.0f * diag[ra];
        dvb[mt] = 512.0f * diag[ra + 8];
    }
    int cnt[4][2];
    #pragma unroll
    for (int mt = 0; mt < 4; mt++) { cnt[mt][0] = 0; cnt[mt][1] = 0; }

    unsigned offA[4], permA[4];
    #pragma unroll
    for (int mt = 0; mt < 4; mt++) {
        int rowA = warp_m * 64 + mt * 16 + (lane & 15);
        offA[mt] = rowA * 128;
        permA[mt] = (rowA & 7);
    }
    const unsigned halfA = lane >> 4;
    unsigned offB[4], permB[4];
    #pragma unroll
    for (int np = 0; np < 4; np++) {
        int rowB = warp_n * 64 + np * 16 + ((lane & 16) >> 1) + (lane & 7);
        offB[np] = A_BYTES + rowB * 128;
        permB[np] = (rowB & 7);
    }
    const unsigned halfB = (lane >> 3) & 1;

    float acc[4][8][4];
    #pragma unroll
    for (int mt = 0; mt < 4; mt++)
        #pragma unroll
        for (int nt = 0; nt < 8; nt++)
            #pragma unroll
            for (int c = 0; c < 4; c++) acc[mt][nt][c] = 0.f;

    auto issue = [&](int idx) {
        int jt = idx >> 3;
        int kc = idx & 7;
        bool f8 = kc >= 4;
        const unsigned* Asrc = f8 ? Af8 : Abf;
        const unsigned* Bsrc = f8 ? Bf8 : Bbf;
        int kbw = (kc & 3) * 32 + lg_q * 4;
        size_t jb = (size_t)(jt0 + jt) * 128 * NWORDS;
        unsigned st = sb + (unsigned)(idx % STAGES) * STAGE_B;
        #pragma unroll
        for (int h = 0; h < 8; h++) {
            int r = lg_r + h * 16;
            CP_ASYNC16(st + r * 128 + swq,
                       __cvta_generic_to_global(Asrc + (size_t)(i0 + r) * NWORDS + kbw));
            CP_ASYNC16(st + A_BYTES + r * 128 + swq,
                       __cvta_generic_to_global(Bsrc + jb + (size_t)r * NWORDS + kbw));
        }
    };

    issue(0); CP_COMMIT();
    issue(1); CP_COMMIT();

    for (int idx = 0; idx < TOTAL; idx++) {
        const int jt = idx >> 3;
        const int kc = idx & 7;

        CP_WAIT1();
        __syncthreads();

        if (idx + 2 < TOTAL) { issue(idx + 2); CP_COMMIT(); }

        const unsigned base = sb + (unsigned)(idx % STAGES) * STAGE_B;
        if (kc < 4) {
            #pragma unroll
            for (int ks = 0; ks < 4; ks++) {
                unsigned a[4][4], b[4][4];
                #pragma unroll
                for (int mt = 0; mt < 4; mt++) {
                    unsigned addr = base + offA[mt] + (((2u*ks + halfA) ^ permA[mt]) << 4);
                    LDSM_X4(a[mt][0], a[mt][1], a[mt][2], a[mt][3], addr);
                }
                #pragma unroll
                for (int np = 0; np < 4; np++) {
                    unsigned addr = base + offB[np] + (((2u*ks + halfB) ^ permB[np]) << 4);
                    LDSM_X4(b[np][0], b[np][1], b[np][2], b[np][3], addr);
                }
                #pragma unroll
                for (int mt = 0; mt < 4; mt++) {
                    #pragma unroll
                    for (int np = 0; np < 4; np++) {
                        MMA16816(acc[mt][np * 2],     a[mt], b[np][0], b[np][1]);
                        MMA16816(acc[mt][np * 2 + 1], a[mt], b[np][2], b[np][3]);
                    }
                }
            }
        } else {
            #pragma unroll
            for (int ks = 0; ks < 4; ks++) {
                unsigned a[4][4], b[4][4];
                #pragma unroll
                for (int mt = 0; mt < 4; mt++) {
                    unsigned addr = base + offA[mt] + (((2u*ks + halfA) ^ permA[mt]) << 4);
                    LDSM_X4(a[mt][0], a[mt][1], a[mt][2], a[mt][3], addr);
                }
                #pragma unroll
                for (int np = 0; np < 4; np++) {
                    unsigned addr = base + offB[np] + (((2u*ks + halfB) ^ permB[np]) << 4);
                    LDSM_X4(b[np][0], b[np][1], b[np][2], b[np][3], addr);
                }
                #pragma unroll
                for (int mt = 0; mt < 4; mt++) {
                    #pragma unroll
                    for (int np = 0; np < 4; np++) {
                        MMAFP832(acc[mt][np * 2],     a[mt], b[np][0], b[np][1]);
                        MMAFP832(acc[mt][np * 2 + 1], a[mt], b[np][2], b[np][3]);
                    }
                }
            }
        }

        if (kc == NCHUNK - 1) {
            int j0 = (jt0 + jt) * 128 + warp_n * 64 + (lane & 3) * 2;
            #pragma unroll
            for (int mt = 0; mt < 4; mt++) {
                int ia = i0 + warp_m * 64 + mt * 16 + (lane >> 2);
                int ib = ia + 8;
                float da = dva[mt], db = dvb[mt];
                int ca = 0, cb = 0;
                #pragma unroll
                for (int nt = 0; nt < 8; nt++) {
                    int j = j0 + nt * 8;
                    float s0 = acc[mt][nt][0], s1 = acc[mt][nt][1];
                    float s2 = acc[mt][nt][2], s3 = acc[mt][nt][3];
                    ca += (j     != ia) && ((s0 > da) || (s0 == da && j     < ia));
                    ca += (j + 1 != ia) && ((s1 > da) || (s1 == da && j + 1 < ia));
                    cb += (j     != ib) && ((s2 > db) || (s2 == db && j     < ib));
                    cb += (j + 1 != ib) && ((s3 > db) || (s3 == db && j + 1 < ib));
                    acc[mt][nt][0] = 0.f; acc[mt][nt][1] = 0.f;
                    acc[mt][nt][2] = 0.f; acc[mt][nt][3] = 0.f;
                }
                cnt[mt][0] += ca;
                cnt[mt][1] += cb;
            }
        }
    }

    __syncthreads();
    #pragma unroll
    for (int mt = 0; mt < 4; mt++) {
        int la = warp_m * 64 + mt * 16 + (lane >> 2);
        atomicAdd(&scnt[la], cnt[mt][0]);
        atomicAdd(&scnt[la + 8], cnt[mt][1]);
    }
    __syncthreads();
    if (t < 128) atomicAdd(&g_cnt[mat][i0 + t], scnt[t]);
}

// ---------------- 5. scalars -------------------------------------------------
__global__ void finalize_kernel(float* __restrict__ out) {
    __shared__ float red[256];
    int t = threadIdx.x;
    for (int m = 0; m < 4; m++) {
        float s = 0.f, q = 0.f;
        #pragma unroll 8
        for (int ch = 0; ch < 64; ch++) { s += g_cs[m][ch][t]; q += g_cq[m][ch][t]; }
        float var = (q - s * s / (float)NROWS) / (float)(NROWS - 1);
        red[t] = sqrtf(fmaxf(var, 0.f));
        __syncthreads();
        for (int off = 128; off; off >>= 1) {
            if (t < off) red[t] += red[t + off];
            __syncthreads();
        }
        if (t == 0) out[1 + m] = red[0] / (float)NC;
        __syncthreads();
    }
    float s1 = 0.f, s2 = 0.f;
    for (int i = t; i < NROWS; i += 256) { s1 += g_d1[i]; s2 += g_d2[i]; }
    red[t] = s1; __syncthreads();
    for (int off = 128; off; off >>= 1) { if (t < off) red[t] += red[t + off]; __syncthreads(); }
    float S1 = red[0]; __syncthreads();
    red[t] = s2; __syncthreads();
    for (int off = 128; off; off >>= 1) { if (t < off) red[t] += red[t + off]; __syncthreads(); }
    if (t == 0) {
        float S2 = red[0];
        out[0] = -0.5f * (S1 / (float)NROWS) - 0.5f * (S2 / (float)NROWS);
    }
}

// ---------------- 6. recall constants + mean_rk writeback --------------------
__global__ void fill_kernel(float* __restrict__ out) {
    int idx = blockIdx.x * 256 + threadIdx.x;
    if (idx < 3 * NROWS) {
        int r = idx / NROWS;
        float val = (r == 0) ? 1.0f : (r == 1) ? 5.0f : 10.0f;
        out[5 + idx] = val;
        out[5 + 4 * NROWS + idx] = val;
    }
    if (idx < 2 * NROWS) {
        int m = idx / NROWS, i = idx - m * NROWS;
        out[5 + (size_t)(m ? 7 : 3) * NROWS + i] = (float)g_cnt[m][i];
    }
}

// ---------------- launch -----------------------------------------------------
extern "C" void kernel_launch(void* const* d_in, const int* in_sizes, int n_in,
                              void* d_out, int out_size) {
    const float* v  = (const float*)d_in[0];
    const float* t  = (const float*)d_in[1];
    const float* pv = (const float*)d_in[2];
    const float* pt = (const float*)d_in[3];
    float* out = (float*)d_out;

    cudaFuncSetAttribute(count_kernel,
                         cudaFuncAttributeMaxDynamicSharedMemorySize, DYN_SMEM);

    normalize_kernel<<<dim3(NROWS / 8, 4), 256>>>(v, t, pv, pt);
    colstats_kernel<<<dim3(64, 4), 256>>>();
    diag_kernel<<<dim3(NROWS / 8), 256>>>();
    count_kernel<<<dim3(64, 2, JSPLIT), 128, DYN_SMEM>>>();
    finalize_kernel<<<1, 256>>>(out);
    fill_kernel<<<(3 * NROWS + 255) / 256, 256>>>(out);
}

// round 8
// speedup vs baseline: 1.0143x; 1.0143x over previous
#include <cuda_runtime.h>
#include <cuda_bf16.h>
#include <math.h>
#include <stdint.h>

#define NROWS 8192
#define NC    256
#define NWORDS (NC/2)          // 128 uint32 (bf16x2) per row

// ---------------- scratch ----------------------------------------------------
__device__ float    g_nrm[4][NROWS * NC];      // normalized fp32 (v,t,pv,pt)
__device__ unsigned g_bhi[4][NROWS * NWORDS];  // bf16 hi, packed bf16x2
__device__ unsigned g_blo[4][NROWS * NWORDS];  // bf16 lo, packed bf16x2
__device__ float    g_d1[NROWS];               // v_i . pt_i
__device__ float    g_d2[NROWS];               // t_i . pv_i
__device__ float    g_cs[4][64][NC];
__device__ float    g_cq[4][64][NC];
__device__ int      g_cnt[2][NROWS];           // global rank counters

// ---------------- small helpers ----------------------------------------------
__device__ __forceinline__ uint32_t smem_u32(const void* p) {
    uint32_t a;
    asm("{ .reg .u64 t; cvta.to.shared.u64 t, %1; cvt.u32.u64 %0, t; }"
        : "=r"(a) : "l"(p));
    return a;
}

#define CP_ASYNC16(dst, src)                                                   \
    asm volatile("cp.async.cg.shared.global [%0], [%1], 16;"                   \
                 :: "r"(dst), "l"(src) : "memory")
#define CP_COMMIT()  asm volatile("cp.async.commit_group;" ::: "memory")
#define CP_WAIT1()   asm volatile("cp.async.wait_group 1;" ::: "memory")

#define LDSM_X4(r0, r1, r2, r3, addr)                                          \
    asm volatile("ldmatrix.sync.aligned.m8n8.x4.shared.b16 {%0,%1,%2,%3}, [%4];" \
                 : "=r"(r0), "=r"(r1), "=r"(r2), "=r"(r3) : "r"(addr))

#define MMA16816(d, a, b0, b1)                                                 \
    asm volatile("mma.sync.aligned.m16n8k16.row.col.f32.bf16.bf16.f32 "        \
                 "{%0,%1,%2,%3}, {%4,%5,%6,%7}, {%8,%9}, {%0,%1,%2,%3};"       \
                 : "+f"((d)[0]), "+f"((d)[1]), "+f"((d)[2]), "+f"((d)[3])      \
                 : "r"((a)[0]), "r"((a)[1]), "r"((a)[2]), "r"((a)[3]),         \
                   "r"(b0), "r"(b1))

// ---------------- 1. normalize + bf16 hi/lo split ---------------------------
__device__ __forceinline__ unsigned pack2(__nv_bfloat16 a, __nv_bfloat16 b) {
    return (unsigned)__bfloat16_as_ushort(a) | ((unsigned)__bfloat16_as_ushort(b) << 16);
}
__device__ __forceinline__ void split_pair(float a, float b, unsigned& hi, unsigned& lo) {
    __nv_bfloat16 ha = __float2bfloat16_rn(a), hb = __float2bfloat16_rn(b);
    float ra = a - __bfloat162float(ha);
    float rb = b - __bfloat162float(hb);
    hi = pack2(ha, hb);
    lo = pack2(__float2bfloat16_rn(ra), __float2bfloat16_rn(rb));
}

__global__ void normalize_kernel(const float* __restrict__ v,
                                 const float* __restrict__ t,
                                 const float* __restrict__ pv,
                                 const float* __restrict__ pt) {
    int y = blockIdx.y;
    const float* src = (y == 0) ? v : (y == 1) ? t : (y == 2) ? pv : pt;
    int warp = threadIdx.x >> 5, lane = threadIdx.x & 31;
    int row = blockIdx.x * 8 + warp;
    const float4* s4 = (const float4*)(src + (size_t)row * NC);
    float4 x0 = s4[lane];
    float4 x1 = s4[lane + 32];
    float ss = x0.x*x0.x + x0.y*x0.y + x0.z*x0.z + x0.w*x0.w
             + x1.x*x1.x + x1.y*x1.y + x1.z*x1.z + x1.w*x1.w;
    #pragma unroll
    for (int o = 16; o; o >>= 1) ss += __shfl_xor_sync(0xffffffffu, ss, o);
    float r = 1.0f / fmaxf(sqrtf(ss), 1e-12f);
    x0.x *= r; x0.y *= r; x0.z *= r; x0.w *= r;
    x1.x *= r; x1.y *= r; x1.z *= r; x1.w *= r;
    float4* d4 = (float4*)(g_nrm[y] + (size_t)row * NC);
    d4[lane] = x0;
    d4[lane + 32] = x1;
    unsigned h, l;
    size_t rb = (size_t)row * NWORDS;
    split_pair(x0.x, x0.y, h, l); g_bhi[y][rb + 2*lane]      = h; g_blo[y][rb + 2*lane]      = l;
    split_pair(x0.z, x0.w, h, l); g_bhi[y][rb + 2*lane + 1]  = h; g_blo[y][rb + 2*lane + 1]  = l;
    split_pair(x1.x, x1.y, h, l); g_bhi[y][rb + 64 + 2*lane] = h; g_blo[y][rb + 64 + 2*lane] = l;
    split_pair(x1.z, x1.w, h, l); g_bhi[y][rb + 65 + 2*lane] = h; g_blo[y][rb + 65 + 2*lane] = l;
}

// ---------------- 2. per-column partial sums --------------------------------
__global__ void colstats_kernel() {
    const float* X = g_nrm[blockIdx.y];
    int col = threadIdx.x;
    int r0 = blockIdx.x * 128;
    float s = 0.f, q = 0.f;
    #pragma unroll 4
    for (int r = 0; r < 128; r++) {
        float x = X[(size_t)(r0 + r) * NC + col];
        s += x; q += x * x;
    }
    g_cs[blockIdx.y][blockIdx.x][col] = s;
    g_cq[blockIdx.y][blockIdx.x][col] = q;
}

// ---------------- 3. diagonals + zero count buffer --------------------------
__global__ void diag_kernel() {
    int warp = threadIdx.x >> 5, lane = threadIdx.x & 31;
    int row = blockIdx.x * 8 + warp;
    int zi = blockIdx.x * 256 + threadIdx.x;
    if (zi < 2 * NROWS) ((int*)g_cnt)[zi] = 0;

    size_t base = (size_t)row * NC;
    const float4* a = (const float4*)(g_nrm[0] + base);
    const float4* b = (const float4*)(g_nrm[3] + base);
    const float4* c = (const float4*)(g_nrm[1] + base);
    const float4* d = (const float4*)(g_nrm[2] + base);
    float4 a0 = a[lane], a1 = a[lane+32], b0 = b[lane], b1 = b[lane+32];
    float4 c0 = c[lane], c1 = c[lane+32], d0 = d[lane], d1 = d[lane+32];
    float s1 = a0.x*b0.x + a0.y*b0.y + a0.z*b0.z + a0.w*b0.w
             + a1.x*b1.x + a1.y*b1.y + a1.z*b1.z + a1.w*b1.w;
    float s2 = c0.x*d0.x + c0.y*d0.y + c0.z*d0.z + c0.w*d0.w
             + c1.x*d1.x + c1.y*d1.y + c1.z*d1.z + c1.w*d1.w;
    #pragma unroll
    for (int o = 16; o; o >>= 1) {
        s1 += __shfl_xor_sync(0xffffffffu, s1, o);
        s2 += __shfl_xor_sync(0xffffffffu, s2, o);
    }
    if (lane == 0) { g_d1[row] = s1; g_d2[row] = s2; }
}

// ---------------- 4. HMMA GEMM + rank count ---------------------------------
// 3-term split GEMM, K'=768. BM=BN=128, BK=64. 256 threads, 8 warps (2x4),
// warp tile 64x32. 3-stage cp.async, 2 CTAs/SM (16 warps/SM = 4/SMSP).
#define A_BYTES  16384
#define B_BYTES  16384
#define STAGE_B  (A_BYTES + B_BYTES)
#define STAGES   3
#define DYN_SMEM (STAGES * STAGE_B + 1024)
#define NCHUNK   12                 // 768 / 64
#define JSPLIT   4
#define NJT      (64 / JSPLIT)      // 16 j-tiles of 128 per CTA
#define TOTAL    (NJT * NCHUNK)

__global__ void __launch_bounds__(256, 2) count_kernel() {
    extern __shared__ char dynsm[];
    __shared__ int scnt[128];

    const int t = threadIdx.x;
    const int lane = t & 31;
    const int wid = t >> 5;
    const int warp_m = wid & 1;          // 0..1 -> 64-row slab
    const int warp_n = wid >> 1;         // 0..3 -> 32-col slab
    const int mat = blockIdx.y;
    const int i0 = blockIdx.x * 128;
    const int jt0 = blockIdx.z * NJT;

    const unsigned* __restrict__ Ahi = g_bhi[mat ? 1 : 0];
    const unsigned* __restrict__ Alo = g_blo[mat ? 1 : 0];
    const unsigned* __restrict__ Bhi = g_bhi[mat ? 2 : 3];
    const unsigned* __restrict__ Blo = g_blo[mat ? 2 : 3];
    const float*    __restrict__ diag = mat ? g_d2 : g_d1;

    const unsigned sb = (smem_u32(dynsm) + 1023u) & ~1023u;

    if (t < 128) scnt[t] = 0;

    // loader: 256 threads. A: 128 rows (4/thread), B: 128 rows (4/thread), 16B each
    const int lg_r = t >> 3;             // 0..31
    const int lg_q = t & 7;
    const unsigned swq = ((unsigned)(lg_q ^ (lg_r & 7))) << 4;   // r+32k keeps r&7

    // per-thread diag values and counters
    float dva[4], dvb[4];
    #pragma unroll
    for (int mt = 0; mt < 4; mt++) {
        int ra = i0 + warp_m * 64 + mt * 16 + (lane >> 2);
        dva[mt] = diag[ra];
        dvb[mt] = diag[ra + 8];
    }
    int cnt[4][2];
    #pragma unroll
    for (int mt = 0; mt < 4; mt++) { cnt[mt][0] = 0; cnt[mt][1] = 0; }

    // ldmatrix address components (within a stage)
    unsigned offA[4], permA[4];
    #pragma unroll
    for (int mt = 0; mt < 4; mt++) {
        int rowA = warp_m * 64 + mt * 16 + (lane & 15);
        offA[mt] = rowA * 128;
        permA[mt] = (rowA & 7);
    }
    const unsigned halfA = lane >> 4;
    unsigned offB[2], permB[2];
    #pragma unroll
    for (int np = 0; np < 2; np++) {
        int rowB = warp_n * 32 + np * 16 + ((lane & 16) >> 1) + (lane & 7);
        offB[np] = A_BYTES + rowB * 128;
        permB[np] = (rowB & 7);
    }
    const unsigned halfB = (lane >> 3) & 1;

    float acc[4][4][4];
    #pragma unroll
    for (int mt = 0; mt < 4; mt++)
        #pragma unroll
        for (int nt = 0; nt < 4; nt++)
            #pragma unroll
            for (int c = 0; c < 4; c++) acc[mt][nt][c] = 0.f;

    auto issue = [&](int idx) {
        int jt  = idx / NCHUNK;
        int kc  = idx - jt * NCHUNK;
        int term = kc >> 2;
        int kbw  = (kc & 3) * 32 + lg_q * 4;
        const unsigned* Asrc = (term < 2) ? Ahi : Alo;
        const unsigned* Bsrc = (term == 1) ? Blo : Bhi;
        size_t jb = (size_t)(jt0 + jt) * 128 * NWORDS;
        unsigned st = sb + (unsigned)(idx % STAGES) * STAGE_B;
        #pragma unroll
        for (int h = 0; h < 4; h++) {
            int r = lg_r + h * 32;
            CP_ASYNC16(st + r * 128 + swq,
                       __cvta_generic_to_global(Asrc + (size_t)(i0 + r) * NWORDS + kbw));
            CP_ASYNC16(st + A_BYTES + r * 128 + swq,
                       __cvta_generic_to_global(Bsrc + jb + (size_t)r * NWORDS + kbw));
        }
    };

    issue(0); CP_COMMIT();
    issue(1); CP_COMMIT();

    for (int idx = 0; idx < TOTAL; idx++) {
        const int jt = idx / NCHUNK;
        const int kc = idx - jt * NCHUNK;

        CP_WAIT1();
        __syncthreads();

        if (idx + 2 < TOTAL) { issue(idx + 2); CP_COMMIT(); }

        const unsigned base = sb + (unsigned)(idx % STAGES) * STAGE_B;
        #pragma unroll
        for (int ks = 0; ks < 4; ks++) {
            unsigned a[4][4], b[2][4];
            #pragma unroll
            for (int mt = 0; mt < 4; mt++) {
                unsigned addr = base + offA[mt] + (((2u*ks + halfA) ^ permA[mt]) << 4);
                LDSM_X4(a[mt][0], a[mt][1], a[mt][2], a[mt][3], addr);
            }
            #pragma unroll
            for (int np = 0; np < 2; np++) {
                unsigned addr = base + offB[np] + (((2u*ks + halfB) ^ permB[np]) << 4);
                LDSM_X4(b[np][0], b[np][1], b[np][2], b[np][3], addr);
            }
            #pragma unroll
            for (int mt = 0; mt < 4; mt++) {
                #pragma unroll
                for (int np = 0; np < 2; np++) {
                    MMA16816(acc[mt][np * 2],     a[mt], b[np][0], b[np][1]);
                    MMA16816(acc[mt][np * 2 + 1], a[mt], b[np][2], b[np][3]);
                }
            }
        }

        if (kc == NCHUNK - 1) {
            int j0 = (jt0 + jt) * 128 + warp_n * 32 + (lane & 3) * 2;
            #pragma unroll
            for (int mt = 0; mt < 4; mt++) {
                int ia = i0 + warp_m * 64 + mt * 16 + (lane >> 2);
                int ib = ia + 8;
                float da = dva[mt], db = dvb[mt];
                int ca = 0, cb = 0;
                #pragma unroll
                for (int nt = 0; nt < 4; nt++) {
                    int j = j0 + nt * 8;
                    float s0 = acc[mt][nt][0], s1 = acc[mt][nt][1];
                    float s2 = acc[mt][nt][2], s3 = acc[mt][nt][3];
                    ca += (j     != ia) && ((s0 > da) || (s0 == da && j     < ia));
                    ca += (j + 1 != ia) && ((s1 > da) || (s1 == da && j + 1 < ia));
                    cb += (j     != ib) && ((s2 > db) || (s2 == db && j     < ib));
                    cb += (j + 1 != ib) && ((s3 > db) || (s3 == db && j + 1 < ib));
                    acc[mt][nt][0] = 0.f; acc[mt][nt][1] = 0.f;
                    acc[mt][nt][2] = 0.f; acc[mt][nt][3] = 0.f;
                }
                cnt[mt][0] += ca;
                cnt[mt][1] += cb;
            }
        }
    }

    __syncthreads();
    #pragma unroll
    for (int mt = 0; mt < 4; mt++) {
        int la = warp_m * 64 + mt * 16 + (lane >> 2);
        atomicAdd(&scnt[la], cnt[mt][0]);
        atomicAdd(&scnt[la + 8], cnt[mt][1]);
    }
    __syncthreads();
    if (t < 128) atomicAdd(&g_cnt[mat][i0 + t], scnt[t]);
}

// ---------------- 5. scalars -------------------------------------------------
__global__ void finalize_kernel(float* __restrict__ out) {
    __shared__ float red[256];
    int t = threadIdx.x;
    for (int m = 0; m < 4; m++) {
        float s = 0.f, q = 0.f;
        #pragma unroll 8
        for (int ch = 0; ch < 64; ch++) { s += g_cs[m][ch][t]; q += g_cq[m][ch][t]; }
        float var = (q - s * s / (float)NROWS) / (float)(NROWS - 1);
        red[t] = sqrtf(fmaxf(var, 0.f));
        __syncthreads();
        for (int off = 128; off; off >>= 1) {
            if (t < off) red[t] += red[t + off];
            __syncthreads();
        }
        if (t == 0) out[1 + m] = red[0] / (float)NC;
        __syncthreads();
    }
    float s1 = 0.f, s2 = 0.f;
    for (int i = t; i < NROWS; i += 256) { s1 += g_d1[i]; s2 += g_d2[i]; }
    red[t] = s1; __syncthreads();
    for (int off = 128; off; off >>= 1) { if (t < off) red[t] += red[t + off]; __syncthreads(); }
    float S1 = red[0]; __syncthreads();
    red[t] = s2; __syncthreads();
    for (int off = 128; off; off >>= 1) { if (t < off) red[t] += red[t + off]; __syncthreads(); }
    if (t == 0) {
        float S2 = red[0];
        out[0] = -0.5f * (S1 / (float)NROWS) - 0.5f * (S2 / (float)NROWS);
    }
}

// ---------------- 6. recall constants + mean_rk writeback --------------------
__global__ void fill_kernel(float* __restrict__ out) {
    int idx = blockIdx.x * 256 + threadIdx.x;
    if (idx < 3 * NROWS) {
        int r = idx / NROWS;
        float val = (r == 0) ? 1.0f : (r == 1) ? 5.0f : 10.0f;
        out[5 + idx] = val;
        out[5 + 4 * NROWS + idx] = val;
    }
    if (idx < 2 * NROWS) {
        int m = idx / NROWS, i = idx - m * NROWS;
        out[5 + (size_t)(m ? 7 : 3) * NROWS + i] = (float)g_cnt[m][i];
    }
}

// ---------------- launch -----------------------------------------------------
extern "C" void kernel_launch(void* const* d_in, const int* in_sizes, int n_in,
                              void* d_out, int out_size) {
    const float* v  = (const float*)d_in[0];
    const float* t  = (const float*)d_in[1];
    const float* pv = (const float*)d_in[2];
    const float* pt = (const float*)d_in[3];
    float* out = (float*)d_out;

    cudaFuncSetAttribute(count_kernel,
                         cudaFuncAttributeMaxDynamicSharedMemorySize, DYN_SMEM);

    normalize_kernel<<<dim3(NROWS / 8, 4), 256>>>(v, t, pv, pt);
    colstats_kernel<<<dim3(64, 4), 256>>>();
    diag_kernel<<<dim3(NROWS / 8), 256>>>();
    count_kernel<<<dim3(64, 2, JSPLIT), 256, DYN_SMEM>>>();
    finalize_kernel<<<1, 256>>>(out);
    fill_kernel<<<(3 * NROWS + 255) / 256, 256>>>(out);
}

// round 9
// speedup vs baseline: 1.2999x; 1.2815x over previous
#include <cuda_runtime.h>
#include <cuda_bf16.h>
#include <math.h>
#include <stdint.h>

#define NROWS 8192
#define NC    256
#define NWORDS (NC/2)          // 128 uint32 (bf16x2) per row

// ---------------- scratch ----------------------------------------------------
__device__ float    g_nrm[4][NROWS * NC];      // normalized fp32 (v,t,pv,pt)
__device__ unsigned g_bhi[4][NROWS * NWORDS];  // bf16 hi, packed bf16x2
__device__ unsigned g_blo[4][NROWS * NWORDS];  // bf16 lo, packed bf16x2
__device__ float    g_d1[NROWS];               // v_i . pt_i
__device__ float    g_d2[NROWS];               // t_i . pv_i
__device__ float    g_cs[4][64][NC];
__device__ float    g_cq[4][64][NC];
__device__ int      g_cnt[2][NROWS];           // global rank counters

// ---------------- small helpers ----------------------------------------------
__device__ __forceinline__ uint32_t smem_u32(const void* p) {
    uint32_t a;
    asm("{ .reg .u64 t; cvta.to.shared.u64 t, %1; cvt.u32.u64 %0, t; }"
        : "=r"(a) : "l"(p));
    return a;
}

#define CP_ASYNC16(dst, src)                                                   \
    asm volatile("cp.async.cg.shared.global [%0], [%1], 16;"                   \
                 :: "r"(dst), "l"(src) : "memory")
#define CP_COMMIT()  asm volatile("cp.async.commit_group;" ::: "memory")
#define CP_WAIT1()   asm volatile("cp.async.wait_group 1;" ::: "memory")

#define LDSM_X4(r0, r1, r2, r3, addr)                                          \
    asm volatile("ldmatrix.sync.aligned.m8n8.x4.shared.b16 {%0,%1,%2,%3}, [%4];" \
                 : "=r"(r0), "=r"(r1), "=r"(r2), "=r"(r3) : "r"(addr))

#define MMA16816(d, a, b0, b1)                                                 \
    asm volatile("mma.sync.aligned.m16n8k16.row.col.f32.bf16.bf16.f32 "        \
                 "{%0,%1,%2,%3}, {%4,%5,%6,%7}, {%8,%9}, {%0,%1,%2,%3};"       \
                 : "+f"((d)[0]), "+f"((d)[1]), "+f"((d)[2]), "+f"((d)[3])      \
                 : "r"((a)[0]), "r"((a)[1]), "r"((a)[2]), "r"((a)[3]),         \
                   "r"(b0), "r"(b1))

// ---------------- 1. normalize + bf16 hi/lo split ---------------------------
__device__ __forceinline__ unsigned pack2(__nv_bfloat16 a, __nv_bfloat16 b) {
    return (unsigned)__bfloat16_as_ushort(a) | ((unsigned)__bfloat16_as_ushort(b) << 16);
}
__device__ __forceinline__ void split_pair(float a, float b, unsigned& hi, unsigned& lo) {
    __nv_bfloat16 ha = __float2bfloat16_rn(a), hb = __float2bfloat16_rn(b);
    float ra = a - __bfloat162float(ha);
    float rb = b - __bfloat162float(hb);
    hi = pack2(ha, hb);
    lo = pack2(__float2bfloat16_rn(ra), __float2bfloat16_rn(rb));
}

__global__ void normalize_kernel(const float* __restrict__ v,
                                 const float* __restrict__ t,
                                 const float* __restrict__ pv,
                                 const float* __restrict__ pt) {
    int y = blockIdx.y;
    const float* src = (y == 0) ? v : (y == 1) ? t : (y == 2) ? pv : pt;
    int warp = threadIdx.x >> 5, lane = threadIdx.x & 31;
    int row = blockIdx.x * 8 + warp;
    const float4* s4 = (const float4*)(src + (size_t)row * NC);
    float4 x0 = s4[lane];
    float4 x1 = s4[lane + 32];
    float ss = x0.x*x0.x + x0.y*x0.y + x0.z*x0.z + x0.w*x0.w
             + x1.x*x1.x + x1.y*x1.y + x1.z*x1.z + x1.w*x1.w;
    #pragma unroll
    for (int o = 16; o; o >>= 1) ss += __shfl_xor_sync(0xffffffffu, ss, o);
    float r = 1.0f / fmaxf(sqrtf(ss), 1e-12f);
    x0.x *= r; x0.y *= r; x0.z *= r; x0.w *= r;
    x1.x *= r; x1.y *= r; x1.z *= r; x1.w *= r;
    float4* d4 = (float4*)(g_nrm[y] + (size_t)row * NC);
    d4[lane] = x0;
    d4[lane + 32] = x1;
    unsigned h, l;
    size_t rb = (size_t)row * NWORDS;
    split_pair(x0.x, x0.y, h, l); g_bhi[y][rb + 2*lane]      = h; g_blo[y][rb + 2*lane]      = l;
    split_pair(x0.z, x0.w, h, l); g_bhi[y][rb + 2*lane + 1]  = h; g_blo[y][rb + 2*lane + 1]  = l;
    split_pair(x1.x, x1.y, h, l); g_bhi[y][rb + 64 + 2*lane] = h; g_blo[y][rb + 64 + 2*lane] = l;
    split_pair(x1.z, x1.w, h, l); g_bhi[y][rb + 65 + 2*lane] = h; g_blo[y][rb + 65 + 2*lane] = l;
}

// ---------------- 2. per-column partial sums --------------------------------
__global__ void colstats_kernel() {
    const float* X = g_nrm[blockIdx.y];
    int col = threadIdx.x;
    int r0 = blockIdx.x * 128;
    float s = 0.f, q = 0.f;
    #pragma unroll 4
    for (int r = 0; r < 128; r++) {
        float x = X[(size_t)(r0 + r) * NC + col];
        s += x; q += x * x;
    }
    g_cs[blockIdx.y][blockIdx.x][col] = s;
    g_cq[blockIdx.y][blockIdx.x][col] = q;
}

// ---------------- 3. diagonals + zero count buffer --------------------------
__global__ void diag_kernel() {
    int warp = threadIdx.x >> 5, lane = threadIdx.x & 31;
    int row = blockIdx.x * 8 + warp;
    int zi = blockIdx.x * 256 + threadIdx.x;
    if (zi < 2 * NROWS) ((int*)g_cnt)[zi] = 0;

    size_t base = (size_t)row * NC;
    const float4* a = (const float4*)(g_nrm[0] + base);
    const float4* b = (const float4*)(g_nrm[3] + base);
    const float4* c = (const float4*)(g_nrm[1] + base);
    const float4* d = (const float4*)(g_nrm[2] + base);
    float4 a0 = a[lane], a1 = a[lane+32], b0 = b[lane], b1 = b[lane+32];
    float4 c0 = c[lane], c1 = c[lane+32], d0 = d[lane], d1 = d[lane+32];
    float s1 = a0.x*b0.x + a0.y*b0.y + a0.z*b0.z + a0.w*b0.w
             + a1.x*b1.x + a1.y*b1.y + a1.z*b1.z + a1.w*b1.w;
    float s2 = c0.x*d0.x + c0.y*d0.y + c0.z*d0.z + c0.w*d0.w
             + c1.x*d1.x + c1.y*d1.y + c1.z*d1.z + c1.w*d1.w;
    #pragma unroll
    for (int o = 16; o; o >>= 1) {
        s1 += __shfl_xor_sync(0xffffffffu, s1, o);
        s2 += __shfl_xor_sync(0xffffffffu, s2, o);
    }
    if (lane == 0) { g_d1[row] = s1; g_d2[row] = s2; }
}

// ---------------- 4. HMMA GEMM + rank count ---------------------------------
// 3-term split GEMM, K'=768. BM=BN=128, BK=64. 128 threads, 4 warps (2x2),
// warp tile 64x64. 3-stage cp.async, 2 CTAs/SM, j-range split 16 ways
// (2048 CTAs -> ~6.9 waves, wave-quantization loss ~1%).
#define A_BYTES  16384
#define B_BYTES  16384
#define STAGE_B  (A_BYTES + B_BYTES)
#define STAGES   3
#define DYN_SMEM (STAGES * STAGE_B + 1024)
#define NCHUNK   12                 // 768 / 64
#define JSPLIT   16
#define NJT      (64 / JSPLIT)      // 4 j-tiles of 128 per CTA
#define TOTAL    (NJT * NCHUNK)

__global__ void __launch_bounds__(128, 2) count_kernel() {
    extern __shared__ char dynsm[];
    __shared__ int scnt[128];

    const int t = threadIdx.x;
    const int lane = t & 31;
    const int wid = t >> 5;
    const int warp_m = wid & 1;          // 0..1 -> 64-row slab
    const int warp_n = wid >> 1;         // 0..1 -> 64-col slab
    const int mat = blockIdx.y;
    const int i0 = blockIdx.x * 128;
    const int jt0 = blockIdx.z * NJT;

    const unsigned* __restrict__ Ahi = g_bhi[mat ? 1 : 0];
    const unsigned* __restrict__ Alo = g_blo[mat ? 1 : 0];
    const unsigned* __restrict__ Bhi = g_bhi[mat ? 2 : 3];
    const unsigned* __restrict__ Blo = g_blo[mat ? 2 : 3];
    const float*    __restrict__ diag = mat ? g_d2 : g_d1;

    const unsigned sb = (smem_u32(dynsm) + 1023u) & ~1023u;

    if (t < 128) scnt[t] = 0;

    const int lg_r = t >> 3;             // 0..15
    const int lg_q = t & 7;
    const unsigned swq = ((unsigned)(lg_q ^ (lg_r & 7))) << 4;

    float dva[4], dvb[4];
    #pragma unroll
    for (int mt = 0; mt < 4; mt++) {
        int ra = i0 + warp_m * 64 + mt * 16 + (lane >> 2);
        dva[mt] = diag[ra];
        dvb[mt] = diag[ra + 8];
    }
    int cnt[4][2];
    #pragma unroll
    for (int mt = 0; mt < 4; mt++) { cnt[mt][0] = 0; cnt[mt][1] = 0; }

    unsigned offA[4], permA[4];
    #pragma unroll
    for (int mt = 0; mt < 4; mt++) {
        int rowA = warp_m * 64 + mt * 16 + (lane & 15);
        offA[mt] = rowA * 128;
        permA[mt] = (rowA & 7);
    }
    const unsigned halfA = lane >> 4;
    unsigned offB[4], permB[4];
    #pragma unroll
    for (int np = 0; np < 4; np++) {
        int rowB = warp_n * 64 + np * 16 + ((lane & 16) >> 1) + (lane & 7);
        offB[np] = A_BYTES + rowB * 128;
        permB[np] = (rowB & 7);
    }
    const unsigned halfB = (lane >> 3) & 1;

    float acc[4][8][4];
    #pragma unroll
    for (int mt = 0; mt < 4; mt++)
        #pragma unroll
        for (int nt = 0; nt < 8; nt++)
            #pragma unroll
            for (int c = 0; c < 4; c++) acc[mt][nt][c] = 0.f;

    auto issue = [&](int idx) {
        int jt  = idx / NCHUNK;
        int kc  = idx - jt * NCHUNK;
        int term = kc >> 2;
        int kbw  = (kc & 3) * 32 + lg_q * 4;
        const unsigned* Asrc = (term < 2) ? Ahi : Alo;
        const unsigned* Bsrc = (term == 1) ? Blo : Bhi;
        size_t jb = (size_t)(jt0 + jt) * 128 * NWORDS;
        unsigned st = sb + (unsigned)(idx % STAGES) * STAGE_B;
        #pragma unroll
        for (int h = 0; h < 8; h++) {
            int r = lg_r + h * 16;
            CP_ASYNC16(st + r * 128 + swq,
                       __cvta_generic_to_global(Asrc + (size_t)(i0 + r) * NWORDS + kbw));
            CP_ASYNC16(st + A_BYTES + r * 128 + swq,
                       __cvta_generic_to_global(Bsrc + jb + (size_t)r * NWORDS + kbw));
        }
    };

    issue(0); CP_COMMIT();
    issue(1); CP_COMMIT();

    for (int idx = 0; idx < TOTAL; idx++) {
        const int jt = idx / NCHUNK;
        const int kc = idx - jt * NCHUNK;

        CP_WAIT1();
        __syncthreads();

        if (idx + 2 < TOTAL) { issue(idx + 2); CP_COMMIT(); }

        const unsigned base = sb + (unsigned)(idx % STAGES) * STAGE_B;
        #pragma unroll
        for (int ks = 0; ks < 4; ks++) {
            unsigned a[4][4], b[4][4];
            #pragma unroll
            for (int mt = 0; mt < 4; mt++) {
                unsigned addr = base + offA[mt] + (((2u*ks + halfA) ^ permA[mt]) << 4);
                LDSM_X4(a[mt][0], a[mt][1], a[mt][2], a[mt][3], addr);
            }
            #pragma unroll
            for (int np = 0; np < 4; np++) {
                unsigned addr = base + offB[np] + (((2u*ks + halfB) ^ permB[np]) << 4);
                LDSM_X4(b[np][0], b[np][1], b[np][2], b[np][3], addr);
            }
            #pragma unroll
            for (int mt = 0; mt < 4; mt++) {
                #pragma unroll
                for (int np = 0; np < 4; np++) {
                    MMA16816(acc[mt][np * 2],     a[mt], b[np][0], b[np][1]);
                    MMA16816(acc[mt][np * 2 + 1], a[mt], b[np][2], b[np][3]);
                }
            }
        }

        if (kc == NCHUNK - 1) {
            int j0 = (jt0 + jt) * 128 + warp_n * 64 + (lane & 3) * 2;
            #pragma unroll
            for (int mt = 0; mt < 4; mt++) {
                int ia = i0 + warp_m * 64 + mt * 16 + (lane >> 2);
                int ib = ia + 8;
                float da = dva[mt], db = dvb[mt];
                int ca = 0, cb = 0;
                #pragma unroll
                for (int nt = 0; nt < 8; nt++) {
                    int j = j0 + nt * 8;
                    float s0 = acc[mt][nt][0], s1 = acc[mt][nt][1];
                    float s2 = acc[mt][nt][2], s3 = acc[mt][nt][3];
                    ca += (j     != ia) && ((s0 > da) || (s0 == da && j     < ia));
                    ca += (j + 1 != ia) && ((s1 > da) || (s1 == da && j + 1 < ia));
                    cb += (j     != ib) && ((s2 > db) || (s2 == db && j     < ib));
                    cb += (j + 1 != ib) && ((s3 > db) || (s3 == db && j + 1 < ib));
                    acc[mt][nt][0] = 0.f; acc[mt][nt][1] = 0.f;
                    acc[mt][nt][2] = 0.f; acc[mt][nt][3] = 0.f;
                }
                cnt[mt][0] += ca;
                cnt[mt][1] += cb;
            }
        }
    }

    __syncthreads();
    #pragma unroll
    for (int mt = 0; mt < 4; mt++) {
        int la = warp_m * 64 + mt * 16 + (lane >> 2);
        atomicAdd(&scnt[la], cnt[mt][0]);
        atomicAdd(&scnt[la + 8], cnt[mt][1]);
    }
    __syncthreads();
    if (t < 128) atomicAdd(&g_cnt[mat][i0 + t], scnt[t]);
}

// ---------------- 5. scalars -------------------------------------------------
__global__ void finalize_kernel(float* __restrict__ out) {
    __shared__ float red[256];
    int t = threadIdx.x;
    for (int m = 0; m < 4; m++) {
        float s = 0.f, q = 0.f;
        #pragma unroll 8
        for (int ch = 0; ch < 64; ch++) { s += g_cs[m][ch][t]; q += g_cq[m][ch][t]; }
        float var = (q - s * s / (float)NROWS) / (float)(NROWS - 1);
        red[t] = sqrtf(fmaxf(var, 0.f));
        __syncthreads();
        for (int off = 128; off; off >>= 1) {
            if (t < off) red[t] += red[t + off];
            __syncthreads();
        }
        if (t == 0) out[1 + m] = red[0] / (float)NC;
        __syncthreads();
    }
    float s1 = 0.f, s2 = 0.f;
    for (int i = t; i < NROWS; i += 256) { s1 += g_d1[i]; s2 += g_d2[i]; }
    red[t] = s1; __syncthreads();
    for (int off = 128; off; off >>= 1) { if (t < off) red[t] += red[t + off]; __syncthreads(); }
    float S1 = red[0]; __syncthreads();
    red[t] = s2; __syncthreads();
    for (int off = 128; off; off >>= 1) { if (t < off) red[t] += red[t + off]; __syncthreads(); }
    if (t == 0) {
        float S2 = red[0];
        out[0] = -0.5f * (S1 / (float)NROWS) - 0.5f * (S2 / (float)NROWS);
    }
}

// ---------------- 6. recall constants + mean_rk writeback --------------------
__global__ void fill_kernel(float* __restrict__ out) {
    int idx = blockIdx.x * 256 + threadIdx.x;
    if (idx < 3 * NROWS) {
        int r = idx / NROWS;
        float val = (r == 0) ? 1.0f : (r == 1) ? 5.0f : 10.0f;
        out[5 + idx] = val;
        out[5 + 4 * NROWS + idx] = val;
    }
    if (idx < 2 * NROWS) {
        int m = idx / NROWS, i = idx - m * NROWS;
        out[5 + (size_t)(m ? 7 : 3) * NROWS + i] = (float)g_cnt[m][i];
    }
}

// ---------------- launch -----------------------------------------------------
extern "C" void kernel_launch(void* const* d_in, const int* in_sizes, int n_in,
                              void* d_out, int out_size) {
    const float* v  = (const float*)d_in[0];
    const float* t  = (const float*)d_in[1];
    const float* pv = (const float*)d_in[2];
    const float* pt = (const float*)d_in[3];
    float* out = (float*)d_out;

    cudaFuncSetAttribute(count_kernel,
                         cudaFuncAttributeMaxDynamicSharedMemorySize, DYN_SMEM);

    normalize_kernel<<<dim3(NROWS / 8, 4), 256>>>(v, t, pv, pt);
    colstats_kernel<<<dim3(64, 4), 256>>>();
    diag_kernel<<<dim3(NROWS / 8), 256>>>();
    count_kernel<<<dim3(64, 2, JSPLIT), 128, DYN_SMEM>>>();
    finalize_kernel<<<1, 256>>>(out);
    fill_kernel<<<(3 * NROWS + 255) / 256, 256>>>(out);
}